// round 2
// baseline (speedup 1.0000x reference)
#include <cuda_runtime.h>
#include <cstdint>

// Problem constants
#define Bq 2
#define Hq 8
#define Sq 2048
#define Dq 64
#define TEMP 8.0f

// Tiling
#define BM 128
#define BN 128
#define NT 512
#define QS 68            // padded row stride for q/k/v smem (floats)
#define ES2 130          // padded row stride for transposed exp tile

typedef unsigned long long u64t;

__device__ __forceinline__ u64t ffma2(u64t a, u64t b, u64t c) {
    u64t d;
    asm("fma.rn.f32x2 %0, %1, %2, %3;" : "=l"(d) : "l"(a), "l"(b), "l"(c));
    return d;
}
__device__ __forceinline__ float2 unpk(u64t a) {
    float2 f;
    asm("mov.b64 {%0, %1}, %2;" : "=f"(f.x), "=f"(f.y) : "l"(a));
    return f;
}
__device__ __forceinline__ u64t dup2(float x) {
    u64t d;
    asm("mov.b64 %0, {%1, %1};" : "=l"(d) : "f"(x));
    return d;
}

__global__ __launch_bounds__(NT, 1)
void attn_main_kernel(const float* __restrict__ q,
                      const float* __restrict__ k,
                      const float* __restrict__ v,
                      const float* __restrict__ cov,
                      const float* __restrict__ lambda_w,
                      const int*   __restrict__ mask,
                      float* __restrict__ out,      // [B,H,S,D]
                      float* __restrict__ attn)     // [B,H,S,S]
{
    extern __shared__ float sm[];
    float* q_s = sm;                    // BM x QS
    float* k_s = q_s + BM * QS;         // BN x QS
    float* v_s = k_s + BN * QS;         // BN x QS
    float* e_s = v_s + BN * QS;         // BN(t) x ES2, layout e_s[t][ty*4+i]

    const int mtile = blockIdx.x;
    const int h     = blockIdx.y;
    const int b     = blockIdx.z;
    const int bh    = b * Hq + h;
    const int tid   = threadIdx.x;
    const int ty    = tid >> 4;   // 0..31
    const int tx    = tid & 15;   // 0..15

    const float lam  = lambda_w[h];
    const float wcov = lam / (lam + 1.0f);
    const float sqk  = 1.0f / ((lam + 1.0f) * TEMP);

    const float* qg    = q    + ((size_t)bh * Sq + (size_t)mtile * BM) * Dq;
    const float* kg    = k    + (size_t)bh * Sq * Dq;
    const float* vg    = v    + (size_t)bh * Sq * Dq;
    const float* covg  = cov  + ((size_t)b * Sq + (size_t)mtile * BM) * Sq;
    const int*   maskg = mask + ((size_t)b * Sq + (size_t)mtile * BM) * Sq;
    float*       attng = attn + ((size_t)bh * Sq + (size_t)mtile * BM) * Sq;
    float*       outg  = out  + ((size_t)bh * Sq + (size_t)mtile * BM) * Dq;

    // ---- load q tile (once) ----
    {
        const int n4 = BM * Dq / 4;  // 2048 float4
        for (int idx = tid; idx < n4; idx += NT) {
            int row = idx >> 4;            // /16
            int dcol = (idx & 15) << 2;    // *4
            float4 val = *(const float4*)&qg[row * Dq + dcol];
            *(float4*)&q_s[row * QS + dcol] = val;
        }
    }

    // AV accumulators: rows paired (i, i+1) -> 2 pairs x 4 cols
    u64t oacc2[2][4];
    float rowsum[4];
#pragma unroll
    for (int i2 = 0; i2 < 2; i2++)
#pragma unroll
        for (int c = 0; c < 4; c++) oacc2[i2][c] = 0ULL;
#pragma unroll
    for (int i = 0; i < 4; i++) rowsum[i] = 0.0f;

    for (int nt = 0; nt < Sq / BN; nt++) {
        const int t0 = nt * BN;

        __syncthreads();  // protect smem from previous AV phase
        {
            const int n4 = BN * Dq / 4;
            for (int idx = tid; idx < n4; idx += NT) {
                int row = idx >> 4;
                int dcol = (idx & 15) << 2;
                float4 kv = *(const float4*)&kg[(size_t)(t0 + row) * Dq + dcol];
                *(float4*)&k_s[row * QS + dcol] = kv;
                float4 vv = *(const float4*)&vg[(size_t)(t0 + row) * Dq + dcol];
                *(float4*)&v_s[row * QS + dcol] = vv;
            }
        }
        __syncthreads();

        // ---- scores: rows sl = ty + i*32 (i<4), cols t = t0 + tx + j*16 (j<8)
        // d-paired f32x2: acc2.lo accumulates even d, .hi odd d
        u64t acc2[4][8];
#pragma unroll
        for (int i = 0; i < 4; i++)
#pragma unroll
            for (int j = 0; j < 8; j++) acc2[i][j] = 0ULL;

#pragma unroll 4
        for (int d = 0; d < Dq; d += 2) {
            u64t qp[4], kp[8];
#pragma unroll
            for (int i = 0; i < 4; i++)
                qp[i] = *(const u64t*)&q_s[(ty + i * 32) * QS + d];
#pragma unroll
            for (int j = 0; j < 8; j++)
                kp[j] = *(const u64t*)&k_s[(tx + j * 16) * QS + d];
#pragma unroll
            for (int i = 0; i < 4; i++)
#pragma unroll
                for (int j = 0; j < 8; j++)
                    acc2[i][j] = ffma2(qp[i], kp[j], acc2[i][j]);
        }

        // ---- epilogue: fold, blend cov, mask, exp, write attn + e_s(T) ----
#pragma unroll
        for (int i = 0; i < 4; i++) {
            const int sl = ty + i * 32;
#pragma unroll
            for (int j = 0; j < 8; j++) {
                const int tl = tx + j * 16;
                const int t = t0 + tl;
                float2 p = unpk(acc2[i][j]);
                float s = p.x + p.y;
                float logit = sqk * s + wcov * covg[(size_t)sl * Sq + t];
                int m = maskg[(size_t)sl * Sq + t];
                float e = (m != 0) ? __expf(logit) : 0.0f;
                rowsum[i] += e;
                attng[(size_t)sl * Sq + t] = e;
                e_s[tl * ES2 + ty * 4 + i] = e;   // transposed: [t][rpos]
            }
        }
        __syncthreads();

        // ---- AV: oacc2[i2][c] pairs rows (2*i2, 2*i2+1); cols tx*4+c ----
#pragma unroll 4
        for (int t = 0; t < BN; t++) {
            float4 vv = *(const float4*)&v_s[t * QS + tx * 4];
            u64t vp[4];
            vp[0] = dup2(vv.x); vp[1] = dup2(vv.y);
            vp[2] = dup2(vv.z); vp[3] = dup2(vv.w);
            u64t ep[2];
            ep[0] = *(const u64t*)&e_s[t * ES2 + ty * 4 + 0];
            ep[1] = *(const u64t*)&e_s[t * ES2 + ty * 4 + 2];
#pragma unroll
            for (int i2 = 0; i2 < 2; i2++)
#pragma unroll
                for (int c = 0; c < 4; c++)
                    oacc2[i2][c] = ffma2(ep[i2], vp[c], oacc2[i2][c]);
        }
    }

    // ---- reduce rowsums across the 16 tx lanes ----
#pragma unroll
    for (int i = 0; i < 4; i++) {
#pragma unroll
        for (int off = 1; off < 16; off <<= 1)
            rowsum[i] += __shfl_xor_sync(0xffffffffu, rowsum[i], off);
    }
    float inv[4];
#pragma unroll
    for (int i = 0; i < 4; i++) inv[i] = 1.0f / rowsum[i];

    // ---- write normalized output ----
#pragma unroll
    for (int i2 = 0; i2 < 2; i2++) {
        const int sl_lo = ty + (2 * i2) * 32;
        const int sl_hi = ty + (2 * i2 + 1) * 32;
        float4 ol, oh;
        float2 p0 = unpk(oacc2[i2][0]);
        float2 p1 = unpk(oacc2[i2][1]);
        float2 p2 = unpk(oacc2[i2][2]);
        float2 p3 = unpk(oacc2[i2][3]);
        ol.x = p0.x * inv[2 * i2];     ol.y = p1.x * inv[2 * i2];
        ol.z = p2.x * inv[2 * i2];     ol.w = p3.x * inv[2 * i2];
        oh.x = p0.y * inv[2 * i2 + 1]; oh.y = p1.y * inv[2 * i2 + 1];
        oh.z = p2.y * inv[2 * i2 + 1]; oh.w = p3.y * inv[2 * i2 + 1];
        *(float4*)&outg[(size_t)sl_lo * Dq + tx * 4] = ol;
        *(float4*)&outg[(size_t)sl_hi * Dq + tx * 4] = oh;
    }

    // ---- fused normalize tail: rescale this block's attn slice (L2-hot).
    // Thread handles rows sl = ty + i*32 (its rowsums), float4 columns
    // tx*4 + u*64, u=0..31 -> coalesced 256B per iteration.
#pragma unroll
    for (int i = 0; i < 4; i++) {
        const int sl = ty + i * 32;
        const float iv = inv[i];
        float4* arow = (float4*)(attng + (size_t)sl * Sq);
#pragma unroll 4
        for (int u = 0; u < Sq / 64; u++) {
            float4 a = arow[tx + u * 16];
            a.x *= iv; a.y *= iv; a.z *= iv; a.w *= iv;
            arow[tx + u * 16] = a;
        }
    }
}

extern "C" void kernel_launch(void* const* d_in, const int* in_sizes, int n_in,
                              void* d_out, int out_size)
{
    const float* q    = (const float*)d_in[0];
    const float* k    = (const float*)d_in[1];
    const float* v    = (const float*)d_in[2];
    const float* cov  = (const float*)d_in[3];
    const float* lam  = (const float*)d_in[4];
    const int*   mask = (const int*)d_in[5];

    float* out  = (float*)d_out;                          // [B,H,S,D]
    float* attn = out + (size_t)Bq * Hq * Sq * Dq;        // [B,H,S,S]

    const int smem = (BM * QS + 2 * BN * QS + BN * ES2) * (int)sizeof(float);
    cudaFuncSetAttribute(attn_main_kernel,
                         cudaFuncAttributeMaxDynamicSharedMemorySize, smem);

    dim3 grid(Sq / BM, Hq, Bq);  // (16, 8, 2)
    attn_main_kernel<<<grid, NT, smem>>>(q, k, v, cov, lam, mask, out, attn);
}

// round 5
// speedup vs baseline: 2.1811x; 2.1811x over previous
#include <cuda_runtime.h>
#include <cstdint>

#define Bq 2
#define Hq 8
#define Sq 2048
#define Dq 64
#define TEMP 8.0f

#define BM 128
#define BN 128
#define NT 512

// smem word offsets (uint32 words)
#define W_Q   0                      // q tf32 [128][68]
#define W_KT  8704                   // k^T tf32 [64][136]  ([d][t])
#define W_VH  17408                  // v^T hi bf16x2 [64][68] ([d][tpair])
#define W_VL  21760                  // v^T lo bf16x2 [64][68]
#define W_EH  26112                  // e hi bf16x2 [128][68] ([row][tpair])
#define W_EL  34816                  // e lo bf16x2 [128][68]
#define W_RS  43520                  // rowsum [4][128] floats
#define SMEM_WORDS 44032
#define SMEM_BYTES (SMEM_WORDS * 4)  // 176128 B

#define EVS 68    // row stride (words) for VH/VL/EH/EL

static __device__ __forceinline__ uint32_t f2tf32(float f) {
    uint32_t r;
    asm("cvt.rna.tf32.f32 %0, %1;" : "=r"(r) : "f"(f));
    return r;
}
static __device__ __forceinline__ uint32_t bf16x2(float hi, float lo) {
    uint32_t r;
    asm("cvt.rn.bf16x2.f32 %0, %1, %2;" : "=r"(r) : "f"(hi), "f"(lo));
    return r;
}
static __device__ __forceinline__ void mma_tf32(float* d, const uint32_t* a,
                                                const uint32_t* b) {
    asm volatile(
        "mma.sync.aligned.m16n8k8.row.col.f32.tf32.tf32.f32 "
        "{%0,%1,%2,%3}, {%4,%5,%6,%7}, {%8,%9}, {%0,%1,%2,%3};"
        : "+f"(d[0]), "+f"(d[1]), "+f"(d[2]), "+f"(d[3])
        : "r"(a[0]), "r"(a[1]), "r"(a[2]), "r"(a[3]), "r"(b[0]), "r"(b[1]));
}
static __device__ __forceinline__ void mma_bf16(float* d, const uint32_t* a,
                                                const uint32_t* b) {
    asm volatile(
        "mma.sync.aligned.m16n8k16.row.col.f32.bf16.bf16.f32 "
        "{%0,%1,%2,%3}, {%4,%5,%6,%7}, {%8,%9}, {%0,%1,%2,%3};"
        : "+f"(d[0]), "+f"(d[1]), "+f"(d[2]), "+f"(d[3])
        : "r"(a[0]), "r"(a[1]), "r"(a[2]), "r"(a[3]), "r"(b[0]), "r"(b[1]));
}

__global__ __launch_bounds__(NT, 1)
void attn_mma_kernel(const float* __restrict__ q,
                     const float* __restrict__ k,
                     const float* __restrict__ v,
                     const float* __restrict__ cov,
                     const float* __restrict__ lambda_w,
                     const int*   __restrict__ mask,
                     float* __restrict__ out,      // [B,H,S,D]
                     float* __restrict__ attn)     // [B,H,S,S]
{
    extern __shared__ uint32_t sw[];
    uint32_t* QW  = sw + W_Q;
    uint32_t* KTW = sw + W_KT;
    uint32_t* VHW = sw + W_VH;
    uint32_t* VLW = sw + W_VL;
    uint32_t* EHW = sw + W_EH;
    uint32_t* ELW = sw + W_EL;
    float*    rs  = (float*)(sw + W_RS);

    const int h     = blockIdx.x;   // innermost -> 8 heads share cov/mask in L2
    const int mtile = blockIdx.y;
    const int b     = blockIdx.z;
    const int bh    = b * Hq + h;
    const int tid   = threadIdx.x;
    const int wid   = tid >> 5;
    const int lane  = tid & 31;
    const int lg    = lane >> 2;    // group 0..7
    const int lt    = lane & 3;     // 0..3

    const int warp_m = wid & 3;     // both phases share this row partition
    const int warp_n = wid >> 2;    // score: 32-col slice | AV: 16-d slice
    const int rm = warp_m * 32;
    const int cn = warp_n * 32;
    const int dn = warp_n * 16;

    const float lam  = lambda_w[h];
    const float wcov = lam / (lam + 1.0f);
    const float sqk  = 1.0f / ((lam + 1.0f) * TEMP);

    const float* qg    = q    + ((size_t)bh * Sq + (size_t)mtile * BM) * Dq;
    const float* kg    = k    + (size_t)bh * Sq * Dq;
    const float* vg    = v    + (size_t)bh * Sq * Dq;
    const float* covg  = cov  + ((size_t)b * Sq + (size_t)mtile * BM) * Sq;
    const int*   maskg = mask + ((size_t)b * Sq + (size_t)mtile * BM) * Sq;
    float*       attng = attn + ((size_t)bh * Sq + (size_t)mtile * BM) * Sq;
    float*       outg  = out  + ((size_t)bh * Sq + (size_t)mtile * BM) * Dq;

    // ---- fill q smem (tf32), once ----
    {
#pragma unroll
        for (int it = 0; it < 4; it++) {
            int idx = tid + it * NT;        // 2048 float4
            int r  = idx >> 4;
            int c4 = (idx & 15) << 2;
            float4 f = *(const float4*)&qg[r * Dq + c4];
            uint4 o;
            o.x = f2tf32(f.x); o.y = f2tf32(f.y);
            o.z = f2tf32(f.z); o.w = f2tf32(f.w);
            *(uint4*)&QW[r * 68 + c4] = o;
        }
    }

    float oacc[2][2][4];    // AV accumulators, persist across tiles
#pragma unroll
    for (int mi = 0; mi < 2; mi++)
#pragma unroll
        for (int nf = 0; nf < 2; nf++)
#pragma unroll
            for (int c = 0; c < 4; c++) oacc[mi][nf][c] = 0.0f;
    float rowsum[4] = {0.0f, 0.0f, 0.0f, 0.0f};

    for (int nt = 0; nt < Sq / BN; nt++) {
        const int t0 = nt * BN;
        __syncthreads();   // protect k/v/e smem from previous AV reads

        // ---- fill k^T (tf32) ----
#pragma unroll
        for (int it = 0; it < 4; it++) {
            int idx = tid + it * NT;        // 2048 float4
            int t  = idx & 127;
            int c4 = (idx >> 7) << 2;
            float4 f = *(const float4*)&kg[(size_t)(t0 + t) * Dq + c4];
            KTW[(c4 + 0) * 136 + t] = f2tf32(f.x);
            KTW[(c4 + 1) * 136 + t] = f2tf32(f.y);
            KTW[(c4 + 2) * 136 + t] = f2tf32(f.z);
            KTW[(c4 + 3) * 136 + t] = f2tf32(f.w);
        }
        // ---- fill v^T split-bf16 (paired t) ----
#pragma unroll
        for (int it = 0; it < 2; it++) {
            int idx = tid + it * NT;        // 1024 items: 64 tp x 16 d4
            int tp = idx & 63;
            int d4 = (idx >> 6) << 2;
            float4 v0 = *(const float4*)&vg[(size_t)(t0 + 2 * tp) * Dq + d4];
            float4 v1 = *(const float4*)&vg[(size_t)(t0 + 2 * tp + 1) * Dq + d4];
            const float e0[4] = {v0.x, v0.y, v0.z, v0.w};
            const float e1[4] = {v1.x, v1.y, v1.z, v1.w};
#pragma unroll
            for (int i = 0; i < 4; i++) {
                uint32_t hp = bf16x2(e1[i], e0[i]);
                float f0 = __uint_as_float(hp << 16);
                float f1 = __uint_as_float(hp & 0xffff0000u);
                uint32_t lp = bf16x2(e1[i] - f1, e0[i] - f0);
                VHW[(d4 + i) * EVS + tp] = hp;
                VLW[(d4 + i) * EVS + tp] = lp;
            }
        }
        __syncthreads();

        // ---- scores: warp tile 32 rows x 32 cols, tf32 mma ----
        float acc[2][4][4];
#pragma unroll
        for (int mi = 0; mi < 2; mi++)
#pragma unroll
            for (int ni = 0; ni < 4; ni++)
#pragma unroll
                for (int c = 0; c < 4; c++) acc[mi][ni][c] = 0.0f;

#pragma unroll
        for (int ks = 0; ks < 8; ks++) {
            const int kd = ks * 8;
            uint32_t a[2][4], bb[4][2];
#pragma unroll
            for (int mi = 0; mi < 2; mi++) {
                const uint32_t* q0 = QW + (rm + mi * 16 + lg) * 68 + kd + lt;
                a[mi][0] = q0[0];
                a[mi][1] = q0[8 * 68];
                a[mi][2] = q0[4];
                a[mi][3] = q0[8 * 68 + 4];
            }
#pragma unroll
            for (int ni = 0; ni < 4; ni++) {
                const uint32_t* kp = KTW + (kd + lt) * 136 + cn + ni * 8 + lg;
                bb[ni][0] = kp[0];
                bb[ni][1] = kp[4 * 136];
            }
#pragma unroll
            for (int mi = 0; mi < 2; mi++)
#pragma unroll
                for (int ni = 0; ni < 4; ni++)
                    mma_tf32(acc[mi][ni], a[mi], bb[ni]);
        }

        // ---- epilogue: blend, mask, exp, write attn, pack e to smem ----
#pragma unroll
        for (int mi = 0; mi < 2; mi++) {
#pragma unroll
            for (int rh = 0; rh < 2; rh++) {
                const int r = rm + mi * 16 + lg + rh * 8;
                const float* cr = covg  + (size_t)r * Sq + t0;
                const int*   mr = maskg + (size_t)r * Sq + t0;
                float*       ar = attng + (size_t)r * Sq + t0;
                uint32_t* ehr = EHW + r * EVS;
                uint32_t* elr = ELW + r * EVS;
                float rsacc = 0.0f;
#pragma unroll
                for (int ni = 0; ni < 4; ni++) {
                    const int c = cn + ni * 8 + 2 * lt;
                    float s0 = acc[mi][ni][rh * 2 + 0];
                    float s1 = acc[mi][ni][rh * 2 + 1];
                    float2 cv = *(const float2*)(cr + c);
                    int2   mv = *(const int2*)(mr + c);
                    float e0 = mv.x ? __expf(fmaf(sqk, s0, wcov * cv.x)) : 0.0f;
                    float e1 = mv.y ? __expf(fmaf(sqk, s1, wcov * cv.y)) : 0.0f;
                    rsacc += e0 + e1;
                    *(float2*)(ar + c) = make_float2(e0, e1);
                    uint32_t hp = bf16x2(e1, e0);
                    float f0 = __uint_as_float(hp << 16);
                    float f1 = __uint_as_float(hp & 0xffff0000u);
                    uint32_t lp = bf16x2(e1 - f1, e0 - f0);
                    const int tpl = c >> 1;
                    ehr[tpl] = hp;
                    elr[tpl] = lp;
                }
                rowsum[mi * 2 + rh] += rsacc;
            }
        }
        __syncthreads();

        // ---- AV: warp tile 32 rows x 16 d, k=128 via 8 k16 steps ----
#pragma unroll
        for (int ks = 0; ks < 8; ks++) {
            const int tpb = ks * 8 + lt;
            uint32_t ah[2][4], al[2][4], bh[2][2], bl[2][2];
#pragma unroll
            for (int mi = 0; mi < 2; mi++) {
                const int base = (rm + mi * 16 + lg) * EVS + tpb;
                ah[mi][0] = EHW[base];
                ah[mi][1] = EHW[base + 8 * EVS];
                ah[mi][2] = EHW[base + 4];
                ah[mi][3] = EHW[base + 8 * EVS + 4];
                al[mi][0] = ELW[base];
                al[mi][1] = ELW[base + 8 * EVS];
                al[mi][2] = ELW[base + 4];
                al[mi][3] = ELW[base + 8 * EVS + 4];
            }
#pragma unroll
            for (int nf = 0; nf < 2; nf++) {
                const int base = (dn + nf * 8 + lg) * EVS + tpb;
                bh[nf][0] = VHW[base];
                bh[nf][1] = VHW[base + 4];
                bl[nf][0] = VLW[base];
                bl[nf][1] = VLW[base + 4];
            }
#pragma unroll
            for (int mi = 0; mi < 2; mi++)
#pragma unroll
                for (int nf = 0; nf < 2; nf++) {
                    mma_bf16(oacc[mi][nf], ah[mi], bh[nf]);
                    mma_bf16(oacc[mi][nf], ah[mi], bl[nf]);
                    mma_bf16(oacc[mi][nf], al[mi], bh[nf]);
                }
        }
    }

    // ---- rowsum: reduce over lane&3 (lanes sharing a row) ----
#pragma unroll
    for (int i = 0; i < 4; i++) {
        rowsum[i] += __shfl_xor_sync(0xffffffffu, rowsum[i], 1);
        rowsum[i] += __shfl_xor_sync(0xffffffffu, rowsum[i], 2);
    }
    if (lt == 0) {
#pragma unroll
        for (int mi = 0; mi < 2; mi++)
#pragma unroll
            for (int rh = 0; rh < 2; rh++)
                rs[warp_n * 128 + rm + mi * 16 + lg + rh * 8] = rowsum[mi * 2 + rh];
    }
    __syncthreads();

    // ---- write normalized output ----
#pragma unroll
    for (int mi = 0; mi < 2; mi++) {
#pragma unroll
        for (int rh = 0; rh < 2; rh++) {
            const int r = rm + mi * 16 + lg + rh * 8;
            const float iv = 1.0f / (rs[r] + rs[128 + r] + rs[256 + r] + rs[384 + r]);
#pragma unroll
            for (int nf = 0; nf < 2; nf++) {
                const int d = dn + nf * 8 + 2 * lt;
                float2 o;
                o.x = oacc[mi][nf][rh * 2 + 0] * iv;
                o.y = oacc[mi][nf][rh * 2 + 1] * iv;
                *(float2*)(outg + (size_t)r * Dq + d) = o;
            }
        }
    }

    // ---- fused normalize tail: scale this block's attn slice ----
    const int rlane = tid >> 7;          // 0..3
    const int ci    = tid & 127;         // float4 col
#pragma unroll 2
    for (int rb = 0; rb < 32; rb++) {
        const int r = rb * 4 + rlane;
        const float iv = 1.0f / (rs[r] + rs[128 + r] + rs[256 + r] + rs[384 + r]);
        float4* arow = (float4*)(attng + (size_t)r * Sq);
        float4 x0 = arow[ci];
        float4 x1 = arow[ci + 128];
        float4 x2 = arow[ci + 256];
        float4 x3 = arow[ci + 384];
        x0.x *= iv; x0.y *= iv; x0.z *= iv; x0.w *= iv;
        x1.x *= iv; x1.y *= iv; x1.z *= iv; x1.w *= iv;
        x2.x *= iv; x2.y *= iv; x2.z *= iv; x2.w *= iv;
        x3.x *= iv; x3.y *= iv; x3.z *= iv; x3.w *= iv;
        arow[ci]       = x0;
        arow[ci + 128] = x1;
        arow[ci + 256] = x2;
        arow[ci + 384] = x3;
    }
}

extern "C" void kernel_launch(void* const* d_in, const int* in_sizes, int n_in,
                              void* d_out, int out_size)
{
    const float* q    = (const float*)d_in[0];
    const float* k    = (const float*)d_in[1];
    const float* v    = (const float*)d_in[2];
    const float* cov  = (const float*)d_in[3];
    const float* lam  = (const float*)d_in[4];
    const int*   mask = (const int*)d_in[5];

    float* out  = (float*)d_out;                          // [B,H,S,D]
    float* attn = out + (size_t)Bq * Hq * Sq * Dq;        // [B,H,S,S]

    cudaFuncSetAttribute(attn_mma_kernel,
                         cudaFuncAttributeMaxDynamicSharedMemorySize, SMEM_BYTES);

    dim3 grid(Hq, Sq / BM, Bq);  // h innermost: heads share cov/mask in L2
    attn_mma_kernel<<<grid, NT, SMEM_BYTES>>>(q, k, v, cov, lam, mask, out, attn);
}

// round 6
// speedup vs baseline: 2.2187x; 1.0172x over previous
#include <cuda_runtime.h>
#include <cstdint>

#define Bq 2
#define Hq 8
#define Sq 2048
#define Dq 64
#define TEMP 8.0f

#define BM 128
#define BN 128
#define NT 512

// smem word offsets (uint32 words)
#define W_Q   0                      // q tf32 [128][68]
#define W_KT  8704                   // k^T tf32 [64][136]  ([d][t])
#define W_VH  17408                  // v^T hi bf16x2 [64][68] ([d][tpair])
#define W_VL  21760                  // v^T lo bf16x2 [64][68]
#define W_EH  26112                  // e hi bf16x2 [128][68] ([row][tpair])
#define W_EL  34816                  // e lo bf16x2 [128][68]
#define W_RS  43520                  // rowsum [4][128] floats
#define SMEM_WORDS 44032
#define SMEM_BYTES (SMEM_WORDS * 4)  // 176128 B

#define EVS 68    // row stride (words) for VH/VL/EH/EL

static __device__ __forceinline__ uint32_t f2tf32(float f) {
    uint32_t r;
    asm("cvt.rna.tf32.f32 %0, %1;" : "=r"(r) : "f"(f));
    return r;
}
static __device__ __forceinline__ uint32_t bf16x2(float hi, float lo) {
    uint32_t r;
    asm("cvt.rn.bf16x2.f32 %0, %1, %2;" : "=r"(r) : "f"(hi), "f"(lo));
    return r;
}
// exp(x) on fma/alu pipes only (no MUFU). Valid for |x| < ~80; logits here
// are bounded (~|x|<25). Magic-number range reduction + degree-5 Taylor.
static __device__ __forceinline__ float fexp(float x) {
    const float L2E = 1.4426950408889634f;
    float t = fmaf(x, L2E, 12582912.0f);          // 1.5*2^23: rounds to int
    int   in = __float_as_int(t);                 // low bits = n (+even magic)
    float n  = t - 12582912.0f;                   // exact
    float z  = fmaf(x, L2E, -n);                  // frac in [-0.5, 0.5]
    float w  = z * 0.6931471805599453f;           // back to natural log scale
    float p  = fmaf(w, 8.3333333e-3f, 4.1666667e-2f);
    p = fmaf(p, w, 0.16666667f);
    p = fmaf(p, w, 0.5f);
    p = fmaf(p, w, 1.0f);
    p = fmaf(p, w, 1.0f);                         // e^w, rel err < 3e-6
    return __int_as_float(__float_as_int(p) + (in << 23));  // * 2^n
}
static __device__ __forceinline__ void mma_tf32(float* d, const uint32_t* a,
                                                const uint32_t* b) {
    asm volatile(
        "mma.sync.aligned.m16n8k8.row.col.f32.tf32.tf32.f32 "
        "{%0,%1,%2,%3}, {%4,%5,%6,%7}, {%8,%9}, {%0,%1,%2,%3};"
        : "+f"(d[0]), "+f"(d[1]), "+f"(d[2]), "+f"(d[3])
        : "r"(a[0]), "r"(a[1]), "r"(a[2]), "r"(a[3]), "r"(b[0]), "r"(b[1]));
}
static __device__ __forceinline__ void mma_bf16(float* d, const uint32_t* a,
                                                const uint32_t* b) {
    asm volatile(
        "mma.sync.aligned.m16n8k16.row.col.f32.bf16.bf16.f32 "
        "{%0,%1,%2,%3}, {%4,%5,%6,%7}, {%8,%9}, {%0,%1,%2,%3};"
        : "+f"(d[0]), "+f"(d[1]), "+f"(d[2]), "+f"(d[3])
        : "r"(a[0]), "r"(a[1]), "r"(a[2]), "r"(a[3]), "r"(b[0]), "r"(b[1]));
}

__global__ __launch_bounds__(NT, 1)
void attn_mma_kernel(const float* __restrict__ q,
                     const float* __restrict__ k,
                     const float* __restrict__ v,
                     const float* __restrict__ cov,
                     const float* __restrict__ lambda_w,
                     const int*   __restrict__ mask,
                     float* __restrict__ out,      // [B,H,S,D]
                     float* __restrict__ attn)     // [B,H,S,S]
{
    extern __shared__ uint32_t sw[];
    uint32_t* QW  = sw + W_Q;
    uint32_t* KTW = sw + W_KT;
    uint32_t* VHW = sw + W_VH;
    uint32_t* VLW = sw + W_VL;
    uint32_t* EHW = sw + W_EH;
    uint32_t* ELW = sw + W_EL;
    float*    rs  = (float*)(sw + W_RS);

    const int h     = blockIdx.x;   // innermost -> 8 heads share cov/mask in L2
    const int mtile = blockIdx.y;
    const int b     = blockIdx.z;
    const int bh    = b * Hq + h;
    const int tid   = threadIdx.x;
    const int wid   = tid >> 5;
    const int lane  = tid & 31;
    const int lg    = lane >> 2;    // group 0..7
    const int lt    = lane & 3;     // 0..3

    const int warp_m = wid & 3;     // both phases share this row partition
    const int warp_n = wid >> 2;    // score: 32-col slice | AV: 16-d slice
    const int rm = warp_m * 32;
    const int cn = warp_n * 32;
    const int dn = warp_n * 16;

    const float lam  = lambda_w[h];
    const float wcov = lam / (lam + 1.0f);
    const float sqk  = 1.0f / ((lam + 1.0f) * TEMP);

    const float* qg    = q    + ((size_t)bh * Sq + (size_t)mtile * BM) * Dq;
    const float* kg    = k    + (size_t)bh * Sq * Dq;
    const float* vg    = v    + (size_t)bh * Sq * Dq;
    const float* covg  = cov  + ((size_t)b * Sq + (size_t)mtile * BM) * Sq;
    const int*   maskg = mask + ((size_t)b * Sq + (size_t)mtile * BM) * Sq;
    float*       attng = attn + ((size_t)bh * Sq + (size_t)mtile * BM) * Sq;
    float*       outg  = out  + ((size_t)bh * Sq + (size_t)mtile * BM) * Dq;

    // ---- fill q smem (tf32), once ----
    {
#pragma unroll
        for (int it = 0; it < 4; it++) {
            int idx = tid + it * NT;        // 2048 float4
            int r  = idx >> 4;
            int c4 = (idx & 15) << 2;
            float4 f = *(const float4*)&qg[r * Dq + c4];
            uint4 o;
            o.x = f2tf32(f.x); o.y = f2tf32(f.y);
            o.z = f2tf32(f.z); o.w = f2tf32(f.w);
            *(uint4*)&QW[r * 68 + c4] = o;
        }
    }

    float oacc[2][2][4];    // AV accumulators, persist across tiles
#pragma unroll
    for (int mi = 0; mi < 2; mi++)
#pragma unroll
        for (int nf = 0; nf < 2; nf++)
#pragma unroll
            for (int c = 0; c < 4; c++) oacc[mi][nf][c] = 0.0f;
    float rowsum[4] = {0.0f, 0.0f, 0.0f, 0.0f};

    for (int nt = 0; nt < Sq / BN; nt++) {
        const int t0 = nt * BN;
        __syncthreads();   // protect k/v/e smem from previous AV reads

        // ---- fill k^T (tf32) ----
#pragma unroll
        for (int it = 0; it < 4; it++) {
            int idx = tid + it * NT;        // 2048 float4
            int t  = idx & 127;
            int c4 = (idx >> 7) << 2;
            float4 f = *(const float4*)&kg[(size_t)(t0 + t) * Dq + c4];
            KTW[(c4 + 0) * 136 + t] = f2tf32(f.x);
            KTW[(c4 + 1) * 136 + t] = f2tf32(f.y);
            KTW[(c4 + 2) * 136 + t] = f2tf32(f.z);
            KTW[(c4 + 3) * 136 + t] = f2tf32(f.w);
        }
        // ---- fill v^T split-bf16 (paired t) ----
#pragma unroll
        for (int it = 0; it < 2; it++) {
            int idx = tid + it * NT;        // 1024 items: 64 tp x 16 d4
            int tp = idx & 63;
            int d4 = (idx >> 6) << 2;
            float4 v0 = *(const float4*)&vg[(size_t)(t0 + 2 * tp) * Dq + d4];
            float4 v1 = *(const float4*)&vg[(size_t)(t0 + 2 * tp + 1) * Dq + d4];
            const float e0[4] = {v0.x, v0.y, v0.z, v0.w};
            const float e1[4] = {v1.x, v1.y, v1.z, v1.w};
#pragma unroll
            for (int i = 0; i < 4; i++) {
                uint32_t hp = bf16x2(e1[i], e0[i]);
                float f0 = __uint_as_float(hp << 16);
                float f1 = __uint_as_float(hp & 0xffff0000u);
                uint32_t lp = bf16x2(e1[i] - f1, e0[i] - f0);
                VHW[(d4 + i) * EVS + tp] = hp;
                VLW[(d4 + i) * EVS + tp] = lp;
            }
        }
        __syncthreads();

        // ---- scores: warp tile 32 rows x 32 cols, tf32 mma ----
        float acc[2][4][4];
#pragma unroll
        for (int mi = 0; mi < 2; mi++)
#pragma unroll
            for (int ni = 0; ni < 4; ni++)
#pragma unroll
                for (int c = 0; c < 4; c++) acc[mi][ni][c] = 0.0f;

#pragma unroll
        for (int ks = 0; ks < 8; ks++) {
            const int kd = ks * 8;
            uint32_t a[2][4], bb[4][2];
#pragma unroll
            for (int mi = 0; mi < 2; mi++) {
                const uint32_t* q0 = QW + (rm + mi * 16 + lg) * 68 + kd + lt;
                a[mi][0] = q0[0];
                a[mi][1] = q0[8 * 68];
                a[mi][2] = q0[4];
                a[mi][3] = q0[8 * 68 + 4];
            }
#pragma unroll
            for (int ni = 0; ni < 4; ni++) {
                const uint32_t* kp = KTW + (kd + lt) * 136 + cn + ni * 8 + lg;
                bb[ni][0] = kp[0];
                bb[ni][1] = kp[4 * 136];
            }
#pragma unroll
            for (int mi = 0; mi < 2; mi++)
#pragma unroll
                for (int ni = 0; ni < 4; ni++)
                    mma_tf32(acc[mi][ni], a[mi], bb[ni]);
        }

        // ---- epilogue: blend, mask, exp, write attn, pack e to smem ----
#pragma unroll
        for (int mi = 0; mi < 2; mi++) {
#pragma unroll
            for (int rh = 0; rh < 2; rh++) {
                const int r = rm + mi * 16 + lg + rh * 8;
                const float* cr = covg  + (size_t)r * Sq + t0;
                const int*   mr = maskg + (size_t)r * Sq + t0;
                float*       ar = attng + (size_t)r * Sq + t0;
                uint32_t* ehr = EHW + r * EVS;
                uint32_t* elr = ELW + r * EVS;
                float rsacc = 0.0f;
#pragma unroll
                for (int ni = 0; ni < 4; ni++) {
                    const int c = cn + ni * 8 + 2 * lt;
                    float s0 = acc[mi][ni][rh * 2 + 0];
                    float s1 = acc[mi][ni][rh * 2 + 1];
                    float2 cv = *(const float2*)(cr + c);
                    int2   mv = *(const int2*)(mr + c);
                    float e0 = mv.x ? fexp(fmaf(sqk, s0, wcov * cv.x)) : 0.0f;
                    float e1 = mv.y ? fexp(fmaf(sqk, s1, wcov * cv.y)) : 0.0f;
                    rsacc += e0 + e1;
                    *(float2*)(ar + c) = make_float2(e0, e1);
                    uint32_t hp = bf16x2(e1, e0);
                    float f0 = __uint_as_float(hp << 16);
                    float f1 = __uint_as_float(hp & 0xffff0000u);
                    uint32_t lp = bf16x2(e1 - f1, e0 - f0);
                    const int tpl = c >> 1;
                    ehr[tpl] = hp;
                    elr[tpl] = lp;
                }
                rowsum[mi * 2 + rh] += rsacc;
            }
        }
        __syncthreads();

        // ---- AV: warp tile 32 rows x 16 d, k=128 via 8 k16 steps ----
#pragma unroll
        for (int ks = 0; ks < 8; ks++) {
            const int tpb = ks * 8 + lt;
            uint32_t ah[2][4], al[2][4], bh[2][2], bl[2][2];
#pragma unroll
            for (int mi = 0; mi < 2; mi++) {
                const int base = (rm + mi * 16 + lg) * EVS + tpb;
                ah[mi][0] = EHW[base];
                ah[mi][1] = EHW[base + 8 * EVS];
                ah[mi][2] = EHW[base + 4];
                ah[mi][3] = EHW[base + 8 * EVS + 4];
                al[mi][0] = ELW[base];
                al[mi][1] = ELW[base + 8 * EVS];
                al[mi][2] = ELW[base + 4];
                al[mi][3] = ELW[base + 8 * EVS + 4];
            }
#pragma unroll
            for (int nf = 0; nf < 2; nf++) {
                const int base = (dn + nf * 8 + lg) * EVS + tpb;
                bh[nf][0] = VHW[base];
                bh[nf][1] = VHW[base + 4];
                bl[nf][0] = VLW[base];
                bl[nf][1] = VLW[base + 4];
            }
#pragma unroll
            for (int mi = 0; mi < 2; mi++)
#pragma unroll
                for (int nf = 0; nf < 2; nf++) {
                    mma_bf16(oacc[mi][nf], ah[mi], bh[nf]);
                    mma_bf16(oacc[mi][nf], ah[mi], bl[nf]);
                    mma_bf16(oacc[mi][nf], al[mi], bh[nf]);
                }
        }
    }

    // ---- rowsum: reduce over lane&3 (lanes sharing a row) ----
#pragma unroll
    for (int i = 0; i < 4; i++) {
        rowsum[i] += __shfl_xor_sync(0xffffffffu, rowsum[i], 1);
        rowsum[i] += __shfl_xor_sync(0xffffffffu, rowsum[i], 2);
    }
    if (lt == 0) {
#pragma unroll
        for (int mi = 0; mi < 2; mi++)
#pragma unroll
            for (int rh = 0; rh < 2; rh++)
                rs[warp_n * 128 + rm + mi * 16 + lg + rh * 8] = rowsum[mi * 2 + rh];
    }
    __syncthreads();

    // ---- write normalized output ----
#pragma unroll
    for (int mi = 0; mi < 2; mi++) {
#pragma unroll
        for (int rh = 0; rh < 2; rh++) {
            const int r = rm + mi * 16 + lg + rh * 8;
            const float iv = 1.0f / (rs[r] + rs[128 + r] + rs[256 + r] + rs[384 + r]);
#pragma unroll
            for (int nf = 0; nf < 2; nf++) {
                const int d = dn + nf * 8 + 2 * lt;
                float2 o;
                o.x = oacc[mi][nf][rh * 2 + 0] * iv;
                o.y = oacc[mi][nf][rh * 2 + 1] * iv;
                *(float2*)(outg + (size_t)r * Dq + d) = o;
            }
        }
    }

    // ---- fused normalize tail: scale this block's attn slice ----
    const int rlane = tid >> 7;          // 0..3
    const int ci    = tid & 127;         // float4 col
#pragma unroll 2
    for (int rb = 0; rb < 32; rb++) {
        const int r = rb * 4 + rlane;
        const float iv = 1.0f / (rs[r] + rs[128 + r] + rs[256 + r] + rs[384 + r]);
        float4* arow = (float4*)(attng + (size_t)r * Sq);
        float4 x0 = arow[ci];
        float4 x1 = arow[ci + 128];
        float4 x2 = arow[ci + 256];
        float4 x3 = arow[ci + 384];
        x0.x *= iv; x0.y *= iv; x0.z *= iv; x0.w *= iv;
        x1.x *= iv; x1.y *= iv; x1.z *= iv; x1.w *= iv;
        x2.x *= iv; x2.y *= iv; x2.z *= iv; x2.w *= iv;
        x3.x *= iv; x3.y *= iv; x3.z *= iv; x3.w *= iv;
        arow[ci]       = x0;
        arow[ci + 128] = x1;
        arow[ci + 256] = x2;
        arow[ci + 384] = x3;
    }
}

extern "C" void kernel_launch(void* const* d_in, const int* in_sizes, int n_in,
                              void* d_out, int out_size)
{
    const float* q    = (const float*)d_in[0];
    const float* k    = (const float*)d_in[1];
    const float* v    = (const float*)d_in[2];
    const float* cov  = (const float*)d_in[3];
    const float* lam  = (const float*)d_in[4];
    const int*   mask = (const int*)d_in[5];

    float* out  = (float*)d_out;                          // [B,H,S,D]
    float* attn = out + (size_t)Bq * Hq * Sq * Dq;        // [B,H,S,S]

    cudaFuncSetAttribute(attn_mma_kernel,
                         cudaFuncAttributeMaxDynamicSharedMemorySize, SMEM_BYTES);

    dim3 grid(Hq, Sq / BM, Bq);  // h innermost: heads share cov/mask in L2
    attn_mma_kernel<<<grid, NT, SMEM_BYTES>>>(q, k, v, cov, lam, mask, out, attn);
}